// round 6
// baseline (speedup 1.0000x reference)
#include <cuda_runtime.h>
#include <cuda_fp16.h>
#include <cstdint>
#include <cstddef>
#include <mma.h>

using namespace nvcuda;

// Problem constants (fixed shapes per reference setup_inputs)
#define N_NODES    100000
#define N_TYPES    7
#define E_PER_TYPE 250000
#define DIM        128
#define N_PAD      100096          // 782 tiles * 128

#define LDP 132                    // smem row stride (floats), pad vs bank conflicts

// Scratch
__device__ __half g_yh[(size_t)N_TYPES * N_PAD * DIM];   // transformed feats (fp16, 179 MB)
__device__ float  g_xt[(size_t)N_PAD * DIM];             // tf32-rounded x, zero-padded rows
__device__ float  g_Wt[N_TYPES * DIM * DIM];             // tf32-rounded W
__device__ float  g_cnt[N_TYPES * N_NODES];
__device__ float  g_inv[N_TYPES * N_NODES];

// ---------------------------------------------------------------------------
// cp.async helpers
// ---------------------------------------------------------------------------
__device__ __forceinline__ void cp_async16(unsigned int dst_smem, const void* src) {
    asm volatile("cp.async.cg.shared.global [%0], [%1], 16;"
                 :: "r"(dst_smem), "l"(src));
}
__device__ __forceinline__ void cp_commit() {
    asm volatile("cp.async.commit_group;");
}
template <int N>
__device__ __forceinline__ void cp_wait() {
    asm volatile("cp.async.wait_group %0;" :: "n"(N));
}

__device__ __forceinline__ unsigned int pack_h2(float a, float b) {
    __half2 h = __floats2half2_rn(a, b);
    return *reinterpret_cast<unsigned int*>(&h);
}

// ---------------------------------------------------------------------------
// Kernel 0: pre-round x (zero-padded to N_PAD rows) and W to tf32.
// ---------------------------------------------------------------------------
__global__ void cvt_kernel(const float4* __restrict__ x4,
                           const float4* __restrict__ W4) {
    const int NX = N_PAD * (DIM / 4);
    const int NW = N_TYPES * DIM * (DIM / 4);
    int idx = blockIdx.x * blockDim.x + threadIdx.x;
    if (idx < NX) {
        int row = idx >> 5;
        float4 v = make_float4(0.f, 0.f, 0.f, 0.f);
        if (row < N_NODES) {
            v = __ldg(&x4[idx]);
            v.x = wmma::__float_to_tf32(v.x);
            v.y = wmma::__float_to_tf32(v.y);
            v.z = wmma::__float_to_tf32(v.z);
            v.w = wmma::__float_to_tf32(v.w);
        }
        ((float4*)g_xt)[idx] = v;
    } else if (idx < NX + NW) {
        int wi = idx - NX;
        float4 v = __ldg(&W4[wi]);
        v.x = wmma::__float_to_tf32(v.x);
        v.y = wmma::__float_to_tf32(v.y);
        v.z = wmma::__float_to_tf32(v.z);
        v.w = wmma::__float_to_tf32(v.w);
        ((float4*)g_Wt)[wi] = v;
    }
}

// ---------------------------------------------------------------------------
// Kernel 1: zero counts (atomics accumulate across graph replays)
// ---------------------------------------------------------------------------
__global__ void zero_cnt_kernel() {
    const int total = N_TYPES * N_NODES;
    const int stride = gridDim.x * blockDim.x;
    for (int i = blockIdx.x * blockDim.x + threadIdx.x; i < total; i += stride)
        g_cnt[i] = 0.f;
}

// ---------------------------------------------------------------------------
// Kernel 2: in-degree per (type, dst). edge_index is int32.
// ---------------------------------------------------------------------------
__global__ void cnt_kernel(const int* __restrict__ ei) {
    int idx = blockIdx.x * blockDim.x + threadIdx.x;
    if (idx >= N_TYPES * E_PER_TYPE) return;
    int t = idx / E_PER_TYPE;
    int e = idx - t * E_PER_TYPE;
    int dst = ei[(size_t)t * 2 * E_PER_TYPE + E_PER_TYPE + e];
    if ((unsigned)dst < (unsigned)N_NODES)
        atomicAdd(&g_cnt[t * N_NODES + dst], 1.0f);
}

// ---------------------------------------------------------------------------
// Kernel 3: out[n,:] = (1/T) * sum_t (cnt>0) b[t,:];  g_inv = 1/(T*max(cnt,1))
// ---------------------------------------------------------------------------
__global__ void init_out_kernel(const float* __restrict__ bg,
                                float4* __restrict__ out4) {
    int idx = blockIdx.x * blockDim.x + threadIdx.x;
    if (idx >= N_NODES * (DIM / 4)) return;
    int n = idx >> 5;
    int q = idx & 31;

    float4 acc = make_float4(0.f, 0.f, 0.f, 0.f);
#pragma unroll
    for (int t = 0; t < N_TYPES; t++) {
        float c = g_cnt[t * N_NODES + n];
        if (q < N_TYPES && q == t)
            g_inv[t * N_NODES + n] = 1.0f / ((float)N_TYPES * fmaxf(c, 1.0f));
        if (c > 0.f) {
            float4 bb = __ldg(((const float4*)bg) + t * (DIM / 4) + q);
            acc.x += bb.x; acc.y += bb.y; acc.z += bb.z; acc.w += bb.w;
        }
    }
    const float s = 1.0f / (float)N_TYPES;
    acc.x *= s; acc.y *= s; acc.z *= s; acc.w *= s;
    out4[(size_t)n * (DIM / 4) + q] = acc;
}

// ---------------------------------------------------------------------------
// Kernel 4: y[t] = x @ W[t] (tf32 wmma), y stored fp16.
// One block per 128-row tile; loops over all 7 types. A tile resident in smem
// for the whole block; W double-buffered via cp.async, prefetch overlaps MMA.
// Dynamic smem: A[128][LDP] + 2x W[128][LDP] = 202.75 KB.
// ---------------------------------------------------------------------------
__global__ __launch_bounds__(256)
void gemm_kernel() {
    extern __shared__ float sm[];
    float* As = sm;                          // [128][LDP]
    float* Wb0 = sm + 128 * LDP;
    float* Wb1 = sm + 2 * 128 * LDP;

    const int tid  = threadIdx.x;
    const int warp = tid >> 5;
    const int wr   = warp >> 2;              // 0..1
    const int wc   = warp & 3;               // 0..3
    const int row0 = blockIdx.x * 128;

    unsigned int As_s  = (unsigned int)__cvta_generic_to_shared(As);
    unsigned int Wb_s[2] = {(unsigned int)__cvta_generic_to_shared(Wb0),
                            (unsigned int)__cvta_generic_to_shared(Wb1)};
    float* Wb_g[2] = {Wb0, Wb1};

    // Group 0: A tile + W0
    {
        const float* xsrc = g_xt + (size_t)row0 * DIM;
#pragma unroll
        for (int i = 0; i < 16; i++) {
            int li = tid + i * 256;          // 0..4095
            int r  = li >> 5;
            int c4 = li & 31;
            cp_async16(As_s + (unsigned int)(r * LDP + c4 * 4) * 4,
                       xsrc + (size_t)r * DIM + c4 * 4);
        }
        const float* w0 = g_Wt;
#pragma unroll
        for (int i = 0; i < 16; i++) {
            int li = tid + i * 256;
            int r  = li >> 5;
            int c4 = li & 31;
            cp_async16(Wb_s[0] + (unsigned int)(r * LDP + c4 * 4) * 4,
                       w0 + (size_t)r * DIM + c4 * 4);
        }
        cp_commit();
    }
    // Group 1: W1 prefetch
    {
        const float* w1 = g_Wt + (size_t)DIM * DIM;
#pragma unroll
        for (int i = 0; i < 16; i++) {
            int li = tid + i * 256;
            int r  = li >> 5;
            int c4 = li & 31;
            cp_async16(Wb_s[1] + (unsigned int)(r * LDP + c4 * 4) * 4,
                       w1 + (size_t)r * DIM + c4 * 4);
        }
        cp_commit();
    }

    for (int t = 0; t < N_TYPES; t++) {
        // Prefetch W_{t+1} into the buffer freed by iteration t-1's epilogue.
        if (t >= 1 && t < N_TYPES - 1) {
            const float* wn = g_Wt + (size_t)(t + 1) * DIM * DIM;
            unsigned int dstb = Wb_s[(t + 1) & 1];
#pragma unroll
            for (int i = 0; i < 16; i++) {
                int li = tid + i * 256;
                int r  = li >> 5;
                int c4 = li & 31;
                cp_async16(dstb + (unsigned int)(r * LDP + c4 * 4) * 4,
                           wn + (size_t)r * DIM + c4 * 4);
            }
            cp_commit();
        }
        if (t < N_TYPES - 1) cp_wait<1>(); else cp_wait<0>();
        __syncthreads();

        float* Ws = Wb_g[t & 1];

        wmma::fragment<wmma::accumulator, 16, 16, 8, float> acc[4][2];
#pragma unroll
        for (int m = 0; m < 4; m++)
#pragma unroll
            for (int n = 0; n < 2; n++) wmma::fill_fragment(acc[m][n], 0.0f);

#pragma unroll
        for (int kk = 0; kk < 16; kk++) {
            wmma::fragment<wmma::matrix_a, 16, 16, 8, wmma::precision::tf32,
                           wmma::row_major> af[4];
            wmma::fragment<wmma::matrix_b, 16, 16, 8, wmma::precision::tf32,
                           wmma::row_major> bf[2];
#pragma unroll
            for (int m = 0; m < 4; m++)
                wmma::load_matrix_sync(af[m],
                    As + (wr * 64 + m * 16) * LDP + kk * 8, LDP);
#pragma unroll
            for (int n = 0; n < 2; n++)
                wmma::load_matrix_sync(bf[n],
                    Ws + (kk * 8) * LDP + wc * 32 + n * 16, LDP);
#pragma unroll
            for (int m = 0; m < 4; m++)
#pragma unroll
                for (int n = 0; n < 2; n++)
                    wmma::mma_sync(acc[m][n], af[m], bf[n], acc[m][n]);
        }
        __syncthreads();   // all warps done reading Ws before overwrite

        // Stage acc (fp32) into Ws as a [128][LDP] tile
#pragma unroll
        for (int m = 0; m < 4; m++)
#pragma unroll
            for (int n = 0; n < 2; n++)
                wmma::store_matrix_sync(
                    Ws + (wr * 64 + m * 16) * LDP + wc * 32 + n * 16,
                    acc[m][n], LDP, wmma::mem_row_major);
        __syncthreads();

        // Convert to fp16 and write coalesced
        __half* ybase = g_yh + ((size_t)t * N_PAD + row0) * DIM;
#pragma unroll
        for (int i = 0; i < 8; i++) {
            int li = tid + i * 256;          // 0..2047
            int g  = li & 15;                // col group of 8
            int r  = li >> 4;                // row
            float4 v0 = *(float4*)&Ws[r * LDP + g * 8];
            float4 v1 = *(float4*)&Ws[r * LDP + g * 8 + 4];
            uint4 u;
            u.x = pack_h2(v0.x, v0.y);
            u.y = pack_h2(v0.z, v0.w);
            u.z = pack_h2(v1.x, v1.y);
            u.w = pack_h2(v1.z, v1.w);
            *(uint4*)(ybase + (size_t)r * DIM + g * 8) = u;
        }
        __syncthreads();   // epilogue reads done before next cp.async reuses Ws
    }
}

// ---------------------------------------------------------------------------
// Kernel 5: scatter. One warp per edge; lane l covers halfs [4l,4l+4).
//   out[dst,:] += y[t,src,:] * inv[t,dst]   via red.global.add.v4.f32
// ---------------------------------------------------------------------------
__global__ __launch_bounds__(512)
void scatter_kernel(const int* __restrict__ ei,
                    float* __restrict__ out) {
    long long wid = ((long long)blockIdx.x * blockDim.x + threadIdx.x) >> 5;
    int lane = threadIdx.x & 31;
    if (wid >= (long long)N_TYPES * E_PER_TYPE) return;
    int t = (int)(wid / E_PER_TYPE);
    int e = (int)(wid - (long long)t * E_PER_TYPE);

    const int* base = ei + (size_t)t * 2 * E_PER_TYPE;
    int src = __ldg(&base[e]);
    int dst = __ldg(&base[E_PER_TYPE + e]);
    if ((unsigned)src >= (unsigned)N_NODES ||
        (unsigned)dst >= (unsigned)N_NODES) return;

    float s = __ldg(&g_inv[t * N_NODES + dst]);
    const uint2* yrow =
        (const uint2*)(g_yh + ((size_t)t * N_PAD + src) * DIM);
    uint2 p = __ldg(&yrow[lane]);
    __half2 h0 = *reinterpret_cast<__half2*>(&p.x);
    __half2 h1 = *reinterpret_cast<__half2*>(&p.y);
    float2 f0 = __half22float2(h0);
    float2 f1 = __half22float2(h1);

    float* q = out + (size_t)dst * DIM + lane * 4;
    asm volatile("red.global.add.v4.f32 [%0], {%1, %2, %3, %4};"
                 :: "l"(q), "f"(f0.x * s), "f"(f0.y * s),
                    "f"(f1.x * s), "f"(f1.y * s)
                 : "memory");
}

// ---------------------------------------------------------------------------
// Inputs: x [100000,128] f32, edge_index [7,2,250000] int32,
//         W [7,128,128] f32, b [7,128] f32.  Output: [100000,128] f32.
// ---------------------------------------------------------------------------
extern "C" void kernel_launch(void* const* d_in, const int* in_sizes, int n_in,
                              void* d_out, int out_size) {
    (void)in_sizes; (void)n_in; (void)out_size;
    const float* x   = (const float*)d_in[0];
    const int*   ei  = (const int*)d_in[1];
    const float* W   = (const float*)d_in[2];
    const float* b   = (const float*)d_in[3];
    float*       out = (float*)d_out;

    const int smem_bytes = 3 * 128 * LDP * 4;   // 202752 < 227KB cap
    cudaFuncSetAttribute(gemm_kernel,
                         cudaFuncAttributeMaxDynamicSharedMemorySize,
                         smem_bytes);

    int ncvt = N_PAD * (DIM / 4) + N_TYPES * DIM * (DIM / 4);
    cvt_kernel<<<(ncvt + 255) / 256, 256>>>((const float4*)x,
                                            (const float4*)W);

    zero_cnt_kernel<<<1024, 256>>>();

    int nedges = N_TYPES * E_PER_TYPE;
    cnt_kernel<<<(nedges + 255) / 256, 256>>>(ei);

    int ninit = N_NODES * (DIM / 4);
    init_out_kernel<<<(ninit + 255) / 256, 256>>>(b, (float4*)out);

    gemm_kernel<<<N_PAD / 128, 256, smem_bytes>>>();

    long long sthreads = (long long)nedges * 32;
    scatter_kernel<<<(int)((sthreads + 511) / 512), 512>>>(ei, out);
}

// round 8
// speedup vs baseline: 1.1154x; 1.1154x over previous
#include <cuda_runtime.h>
#include <cuda_fp16.h>
#include <cstdint>
#include <cstddef>
#include <mma.h>

using namespace nvcuda;

#define N_NODES    100000
#define N_TYPES    7
#define E_PER_TYPE 250000
#define DIM        128
#define N_PAD      100096          // 782 tiles * 128

#define LDA 36                     // A-stage row stride (floats)
#define LDB 132                    // W-stage row stride
#define LDS 132                    // epilogue staging row stride

// Scratch
__device__ __half g_yh[(size_t)N_TYPES * N_PAD * DIM];   // y fp16 (179 MB)
__device__ float  g_xt[(size_t)N_PAD * DIM];             // tf32-rounded x (padded)
__device__ float  g_Wt[N_TYPES * DIM * DIM];             // tf32-rounded W
__device__ float  g_cnt[N_TYPES * N_NODES];
__device__ float  g_inv[N_TYPES * N_NODES];

// ---------------------------------------------------------------------------
// helpers
// ---------------------------------------------------------------------------
__device__ __forceinline__ void cp_async16(unsigned int dst_smem, const void* src) {
    asm volatile("cp.async.cg.shared.global [%0], [%1], 16;"
                 :: "r"(dst_smem), "l"(src));
}
__device__ __forceinline__ void cp_commit() {
    asm volatile("cp.async.commit_group;");
}
template <int N>
__device__ __forceinline__ void cp_wait() {
    asm volatile("cp.async.wait_group %0;" :: "n"(N));
}
__device__ __forceinline__ unsigned int pack_h2(float a, float b) {
    __half2 h = __floats2half2_rn(a, b);
    return *reinterpret_cast<unsigned int*>(&h);
}

// ---------------------------------------------------------------------------
// Kernel 0: pre-round x (zero-padded) and W to tf32; also zero g_cnt.
// ---------------------------------------------------------------------------
__global__ void cvt_kernel(const float4* __restrict__ x4,
                           const float4* __restrict__ W4) {
    const int NX = N_PAD * (DIM / 4);
    const int NW = N_TYPES * DIM * (DIM / 4);
    int idx = blockIdx.x * blockDim.x + threadIdx.x;
    if (idx < NX) {
        int row = idx >> 5;
        float4 v = make_float4(0.f, 0.f, 0.f, 0.f);
        if (row < N_NODES) {
            v = __ldg(&x4[idx]);
            v.x = wmma::__float_to_tf32(v.x);
            v.y = wmma::__float_to_tf32(v.y);
            v.z = wmma::__float_to_tf32(v.z);
            v.w = wmma::__float_to_tf32(v.w);
        }
        ((float4*)g_xt)[idx] = v;
    } else if (idx < NX + NW) {
        int wi = idx - NX;
        float4 v = __ldg(&W4[wi]);
        v.x = wmma::__float_to_tf32(v.x);
        v.y = wmma::__float_to_tf32(v.y);
        v.z = wmma::__float_to_tf32(v.z);
        v.w = wmma::__float_to_tf32(v.w);
        ((float4*)g_Wt)[wi] = v;
    }
    if (idx < N_TYPES * N_NODES) g_cnt[idx] = 0.f;   // zero counts (replay-safe)
}

// ---------------------------------------------------------------------------
// Kernel 1: in-degree per (type, dst). edge_index is int32.
// ---------------------------------------------------------------------------
__global__ void cnt_kernel(const int* __restrict__ ei) {
    int idx = blockIdx.x * blockDim.x + threadIdx.x;
    if (idx >= N_TYPES * E_PER_TYPE) return;
    int t = idx / E_PER_TYPE;
    int e = idx - t * E_PER_TYPE;
    int dst = ei[(size_t)t * 2 * E_PER_TYPE + E_PER_TYPE + e];
    if ((unsigned)dst < (unsigned)N_NODES)
        atomicAdd(&g_cnt[t * N_NODES + dst], 1.0f);
}

// ---------------------------------------------------------------------------
// Kernel 2: g_inv = 1 / (T * max(cnt,1))  (fully coalesced)
// ---------------------------------------------------------------------------
__global__ void inv_kernel() {
    int i = blockIdx.x * blockDim.x + threadIdx.x;
    if (i < N_TYPES * N_NODES)
        g_inv[i] = 1.0f / ((float)N_TYPES * fmaxf(g_cnt[i], 1.0f));
}

// ---------------------------------------------------------------------------
// Kernel 3: out[n,:] = (1/T) * sum_t (cnt[t,n]>0) * b[t,:]   (bias init)
// b staged in smem; 7 independent cnt loads (MLP); branch-free FMA.
// ---------------------------------------------------------------------------
__global__ __launch_bounds__(256)
void init_out_kernel(const float* __restrict__ bg, float4* __restrict__ out4) {
    __shared__ float4 bs[N_TYPES * 32];
    int tid = threadIdx.x;
    if (tid < N_TYPES * 32) bs[tid] = __ldg(((const float4*)bg) + tid);
    __syncthreads();
    int idx = blockIdx.x * blockDim.x + tid;
    if (idx >= N_NODES * (DIM / 4)) return;
    int n = idx >> 5;
    int q = idx & 31;

    float c[N_TYPES];
#pragma unroll
    for (int t = 0; t < N_TYPES; t++) c[t] = g_cnt[t * N_NODES + n];

    float4 acc = make_float4(0.f, 0.f, 0.f, 0.f);
#pragma unroll
    for (int t = 0; t < N_TYPES; t++) {
        float f = (c[t] > 0.f) ? (1.0f / (float)N_TYPES) : 0.f;
        float4 bb = bs[t * 32 + q];
        acc.x = fmaf(f, bb.x, acc.x);
        acc.y = fmaf(f, bb.y, acc.y);
        acc.z = fmaf(f, bb.z, acc.z);
        acc.w = fmaf(f, bb.w, acc.w);
    }
    out4[(size_t)n * (DIM / 4) + q] = acc;
}

// ---------------------------------------------------------------------------
// Kernel 4: y[t,tile] = x_tile @ W[t] (tf32 wmma), y stored fp16.
// Grid (7 types, 782 tiles): types-fastest so 7 blocks share each A tile in L2.
// BK=32 double-buffered cp.async pipeline: prefetch stage k+1 during MMA(k).
// Smem: A 2x[128][LDA] + W 2x[32][LDB] = 70.6 KB (epilogue staging reuses it).
// ---------------------------------------------------------------------------
__global__ __launch_bounds__(256, 2)
void gemm_kernel() {
    extern __shared__ float sm[];
    float* Ab[2] = {sm, sm + 128 * LDA};
    float* Wb[2] = {sm + 2 * 128 * LDA, sm + 2 * 128 * LDA + 32 * LDB};

    const int t    = blockIdx.x;
    const int row0 = blockIdx.y * 128;
    const int tid  = threadIdx.x;
    const int warp = tid >> 5;
    const int wr   = warp >> 2;              // 0..1
    const int wc   = warp & 3;               // 0..3

    unsigned int sAb[2] = {(unsigned int)__cvta_generic_to_shared(Ab[0]),
                           (unsigned int)__cvta_generic_to_shared(Ab[1])};
    unsigned int sWb[2] = {(unsigned int)__cvta_generic_to_shared(Wb[0]),
                           (unsigned int)__cvta_generic_to_shared(Wb[1])};

    const float* Asrc = g_xt + (size_t)row0 * DIM;
    const float* Wsrc = g_Wt + (size_t)t * DIM * DIM;

    // stage loader: A chunk [128][32], W chunk [32][128]
    auto load_stage = [&](int k0, int buf) {
#pragma unroll
        for (int i = 0; i < 4; i++) {
            int li = tid + i * 256;          // 0..1023
            int r  = li >> 3;                // 0..127
            int c4 = li & 7;                 // 0..7
            cp_async16(sAb[buf] + (unsigned int)(r * LDA + c4 * 4) * 4,
                       Asrc + (size_t)r * DIM + k0 + c4 * 4);
        }
#pragma unroll
        for (int i = 0; i < 4; i++) {
            int li = tid + i * 256;
            int r  = li >> 5;                // 0..31
            int c4 = li & 31;                // 0..31
            cp_async16(sWb[buf] + (unsigned int)(r * LDB + c4 * 4) * 4,
                       Wsrc + (size_t)(k0 + r) * DIM + c4 * 4);
        }
        cp_commit();
    };

    wmma::fragment<wmma::accumulator, 16, 16, 8, float> acc[4][2];
#pragma unroll
    for (int m = 0; m < 4; m++)
#pragma unroll
        for (int n = 0; n < 2; n++) wmma::fill_fragment(acc[m][n], 0.0f);

    load_stage(0, 0);

#pragma unroll
    for (int ks = 0; ks < 4; ks++) {
        cp_wait<0>();
        __syncthreads();                     // stage ks ready; prior reads done
        if (ks < 3) load_stage((ks + 1) * 32, (ks + 1) & 1);  // overlap w/ MMA

        float* Ac = Ab[ks & 1];
        float* Wc = Wb[ks & 1];
#pragma unroll
        for (int sk = 0; sk < 4; sk++) {
            wmma::fragment<wmma::matrix_a, 16, 16, 8, wmma::precision::tf32,
                           wmma::row_major> af[4];
            wmma::fragment<wmma::matrix_b, 16, 16, 8, wmma::precision::tf32,
                           wmma::row_major> bf[2];
#pragma unroll
            for (int m = 0; m < 4; m++)
                wmma::load_matrix_sync(af[m],
                    Ac + (wr * 64 + m * 16) * LDA + sk * 8, LDA);
#pragma unroll
            for (int n = 0; n < 2; n++)
                wmma::load_matrix_sync(bf[n],
                    Wc + (sk * 8) * LDB + wc * 32 + n * 16, LDB);
#pragma unroll
            for (int m = 0; m < 4; m++)
#pragma unroll
                for (int n = 0; n < 2; n++)
                    wmma::mma_sync(acc[m][n], af[m], bf[n], acc[m][n]);
        }
    }

    __syncthreads();                         // done reading stages; reuse as staging
    float* stg = sm;                         // [128][LDS]
#pragma unroll
    for (int m = 0; m < 4; m++)
#pragma unroll
        for (int n = 0; n < 2; n++)
            wmma::store_matrix_sync(
                stg + (wr * 64 + m * 16) * LDS + wc * 32 + n * 16,
                acc[m][n], LDS, wmma::mem_row_major);
    __syncthreads();

    __half* ybase = g_yh + ((size_t)t * N_PAD + row0) * DIM;
#pragma unroll
    for (int i = 0; i < 8; i++) {
        int li = tid + i * 256;              // 0..2047
        int r  = li >> 4;                    // 0..127
        int g  = li & 15;                    // col group of 8
        float4 v0 = *(float4*)&stg[r * LDS + g * 8];
        float4 v1 = *(float4*)&stg[r * LDS + g * 8 + 4];
        uint4 u;
        u.x = pack_h2(v0.x, v0.y);
        u.y = pack_h2(v0.z, v0.w);
        u.z = pack_h2(v1.x, v1.y);
        u.w = pack_h2(v1.z, v1.w);
        *(uint4*)(ybase + (size_t)r * DIM + g * 8) = u;
    }
}

// ---------------------------------------------------------------------------
// Kernel 5: scatter. 2 edges per warp; 16 lanes per edge, each lane loads
// uint4 (8 halfs), converts, scales, and issues 2x red.global.add.v4.f32.
// ---------------------------------------------------------------------------
__global__ __launch_bounds__(256)
void scatter_kernel(const int* __restrict__ ei, float* __restrict__ out) {
    long long gt = (long long)blockIdx.x * blockDim.x + threadIdx.x;
    long long edge = gt >> 4;                // 16 lanes per edge
    int sub = threadIdx.x & 15;
    if (edge >= (long long)N_TYPES * E_PER_TYPE) return;
    int t = (int)(edge / E_PER_TYPE);
    int e = (int)(edge - (long long)t * E_PER_TYPE);

    const int* base = ei + (size_t)t * 2 * E_PER_TYPE;
    int src = __ldg(&base[e]);
    int dst = __ldg(&base[E_PER_TYPE + e]);
    if ((unsigned)src >= (unsigned)N_NODES ||
        (unsigned)dst >= (unsigned)N_NODES) return;

    float s = __ldg(&g_inv[t * N_NODES + dst]);
    const uint4* yrow = (const uint4*)(g_yh + ((size_t)t * N_PAD + src) * DIM);
    uint4 p = __ldg(&yrow[sub]);             // 16 B = 8 halfs

    __half2 h0 = *reinterpret_cast<__half2*>(&p.x);
    __half2 h1 = *reinterpret_cast<__half2*>(&p.y);
    __half2 h2 = *reinterpret_cast<__half2*>(&p.z);
    __half2 h3 = *reinterpret_cast<__half2*>(&p.w);
    float2 f0 = __half22float2(h0);
    float2 f1 = __half22float2(h1);
    float2 f2 = __half22float2(h2);
    float2 f3 = __half22float2(h3);

    float* q = out + (size_t)dst * DIM + sub * 8;
    asm volatile("red.global.add.v4.f32 [%0], {%1, %2, %3, %4};"
                 :: "l"(q), "f"(f0.x * s), "f"(f0.y * s),
                    "f"(f1.x * s), "f"(f1.y * s) : "memory");
    asm volatile("red.global.add.v4.f32 [%0], {%1, %2, %3, %4};"
                 :: "l"(q + 4), "f"(f2.x * s), "f"(f2.y * s),
                    "f"(f3.x * s), "f"(f3.y * s) : "memory");
}

// ---------------------------------------------------------------------------
// Inputs: x [100000,128] f32, edge_index [7,2,250000] int32,
//         W [7,128,128] f32, b [7,128] f32.  Output: [100000,128] f32.
// ---------------------------------------------------------------------------
extern "C" void kernel_launch(void* const* d_in, const int* in_sizes, int n_in,
                              void* d_out, int out_size) {
    (void)in_sizes; (void)n_in; (void)out_size;
    const float* x   = (const float*)d_in[0];
    const int*   ei  = (const int*)d_in[1];
    const float* W   = (const float*)d_in[2];
    const float* b   = (const float*)d_in[3];
    float*       out = (float*)d_out;

    const int smem_bytes = (2 * 128 * LDA + 2 * 32 * LDB) * 4;   // 70656
    cudaFuncSetAttribute(gemm_kernel,
                         cudaFuncAttributeMaxDynamicSharedMemorySize,
                         smem_bytes);

    int ncvt = N_PAD * (DIM / 4) + N_TYPES * DIM * (DIM / 4);
    cvt_kernel<<<(ncvt + 255) / 256, 256>>>((const float4*)x,
                                            (const float4*)W);

    int nedges = N_TYPES * E_PER_TYPE;
    cnt_kernel<<<(nedges + 255) / 256, 256>>>(ei);

    inv_kernel<<<(N_TYPES * N_NODES + 255) / 256, 256>>>();

    int ninit = N_NODES * (DIM / 4);
    init_out_kernel<<<(ninit + 255) / 256, 256>>>(b, (float4*)out);

    dim3 ggrid(N_TYPES, N_PAD / 128);
    gemm_kernel<<<ggrid, 256, smem_bytes>>>();

    long long sthreads = (long long)nedges * 16;
    scatter_kernel<<<(int)((sthreads + 255) / 256), 256>>>(ei, out);
}